// round 1
// baseline (speedup 1.0000x reference)
#include <cuda_runtime.h>
#include <math.h>

// Problem constants
#define BSN   100      // B*S = 20*5
#define CCH   640      // channels
#define W_IN  19
#define NW    5
#define P25   25       // NW*NW
#define META_PER_BS (2 * CCH * P25)   // 32000 floats per (b,s)
#define META_TOTAL  (BSN * META_PER_BS) // 3,200,000
#define N_CH_IMG (2 * BSN * CCH)      // 128000 channel-images (s then q)

// Adaptive pool 19 -> 5 bin boundaries (start inclusive, end exclusive)
// i: start = (i*19)/5, end = ceil((i+1)*19/5)
// -> {0,3,7,11,15} .. {4,8,12,16,19}, lengths {4,5,5,5,4}

__global__ __launch_bounds__(256) void pool_kernel(
    const float* __restrict__ s_in,
    const float* __restrict__ q_in,
    float* __restrict__ out)   // d_out base; meta region at offset 0
{
    int n = blockIdx.x * blockDim.x + threadIdx.x;
    if (n >= N_CH_IMG) return;

    const int sel = (n >= BSN * CCH) ? 1 : 0;      // 0 = support, 1 = query
    const int idx = n - sel * (BSN * CCH);
    const int bs  = idx / CCH;
    const int c   = idx - bs * CCH;

    const float* __restrict__ src =
        (sel ? q_in : s_in) + (size_t)idx * (W_IN * W_IN);

    const int BSTART[NW] = {0, 3, 7, 11, 15};
    const int BEND[NW]   = {4, 8, 12, 16, 19};
    const float INVLEN[NW] = {0.25f, 0.2f, 0.2f, 0.2f, 0.25f};

    float acc[NW][NW];
#pragma unroll
    for (int i = 0; i < NW; i++)
#pragma unroll
        for (int j = 0; j < NW; j++)
            acc[i][j] = 0.0f;

#pragma unroll
    for (int r = 0; r < W_IN; r++) {
        float row[W_IN];
#pragma unroll
        for (int w = 0; w < W_IN; w++)
            row[w] = src[r * W_IN + w];

        float cs[NW];
#pragma unroll
        for (int j = 0; j < NW; j++) {
            float v = 0.0f;
#pragma unroll
            for (int w = BSTART[j]; w < BEND[j]; w++)
                v += row[w];
            cs[j] = v;
        }
        // add this row's col-sums into every row-bin containing r
#pragma unroll
        for (int i = 0; i < NW; i++) {
            if (r >= BSTART[i] && r < BEND[i]) {
#pragma unroll
                for (int j = 0; j < NW; j++)
                    acc[i][j] += cs[j];
            }
        }
    }

    float* __restrict__ dst =
        out + (size_t)bs * META_PER_BS + (size_t)(sel * CCH + c) * P25;
#pragma unroll
    for (int i = 0; i < NW; i++) {
        const float ri = INVLEN[i];
#pragma unroll
        for (int j = 0; j < NW; j++)
            dst[i * NW + j] = acc[i][j] * ri * INVLEN[j];
    }
}

// ---------------------------------------------------------------------------
// Kernel 2: per-(b,s) all-pairs cosine similarity + max over query positions.
// Reads the pooled data back out of d_out's meta region (written by kernel 1).
// Dynamic smem: 32000 floats (sf[640*25] then qf[640*25]) = 128000 bytes.
// ---------------------------------------------------------------------------
__global__ __launch_bounds__(1024) void cosine_kernel(
    const float* __restrict__ meta,   // d_out base (meta region)
    float* __restrict__ out)          // d_out + META_TOTAL
{
    extern __shared__ float smem[];   // [2 * CCH * P25]
    float* __restrict__ sf = smem;                  // [c*25 + p]
    float* __restrict__ qf = smem + CCH * P25;      // [c*25 + q]

    __shared__ float sn[P25];
    __shared__ float qn[P25];
    __shared__ float simbuf[P25 * P25];

    const int bs  = blockIdx.x;
    const int tid = threadIdx.x;
    const float* __restrict__ base = meta + (size_t)bs * META_PER_BS;

    // stage pooled tile: channels 0..639 are support, 640..1279 are query
    for (int i = tid; i < META_PER_BS; i += blockDim.x)
        smem[i] = base[i];
    __syncthreads();

    // norms over channels: threads 0..24 -> sn, 25..49 -> qn
    if (tid < 2 * P25) {
        const int p = tid % P25;
        const float* __restrict__ f = (tid >= P25) ? qf : sf;
        float v = 0.0f;
#pragma unroll 8
        for (int c = 0; c < CCH; c++) {
            float x = f[c * P25 + p];
            v += x * x;
        }
        if (tid >= P25) qn[p] = sqrtf(v);
        else            sn[p] = sqrtf(v);
    }
    __syncthreads();

    // all-pairs dot products: thread (p,q), p = tid/25, q = tid%25
    if (tid < P25 * P25) {
        const int p = tid / P25;
        const int q = tid - p * P25;
        float d = 0.0f;
#pragma unroll 8
        for (int c = 0; c < CCH; c++)
            d += sf[c * P25 + p] * qf[c * P25 + q];
        const float den = fmaxf(sn[p] * qn[q], 1e-8f);
        simbuf[tid] = d / den;
    }
    __syncthreads();

    // max over query positions q for each support position p
    if (tid < P25) {
        float m = -INFINITY;
#pragma unroll
        for (int q = 0; q < P25; q++)
            m = fmaxf(m, simbuf[tid * P25 + q]);
        out[bs * P25 + tid] = m;
    }
}

extern "C" void kernel_launch(void* const* d_in, const int* in_sizes, int n_in,
                              void* d_out, int out_size)
{
    const float* s_in = (const float*)d_in[0];
    const float* q_in = (const float*)d_in[1];
    float* out = (float*)d_out;

    // opt into >48KB dynamic shared memory for the cosine kernel
    static int smem_bytes = 2 * CCH * P25 * (int)sizeof(float); // 128000
    cudaFuncSetAttribute(cosine_kernel,
                         cudaFuncAttributeMaxDynamicSharedMemorySize,
                         smem_bytes);

    // Kernel 1: pool both inputs directly into meta region of d_out
    {
        const int threads = 256;
        const int blocks = (N_CH_IMG + threads - 1) / threads; // 500
        pool_kernel<<<blocks, threads>>>(s_in, q_in, out);
    }

    // Kernel 2: cosine similarity + max pool -> out region
    {
        cosine_kernel<<<BSN, 1024, smem_bytes>>>(out, out + META_TOTAL);
    }
}

// round 2
// speedup vs baseline: 1.9163x; 1.9163x over previous
#include <cuda_runtime.h>
#include <math.h>

#define BSN   100
#define CCH   640
#define W_IN  19
#define IMG   (W_IN * W_IN)           // 361
#define NW    5
#define P25   25
#define META_PER_BS (2 * CCH * P25)   // 32000
#define META_TOTAL  (BSN * META_PER_BS)
#define HALF_IMGS   (BSN * CCH)       // 64000 images per tensor

// ---------------------------------------------------------------------------
// Kernel 1: adaptive avg pool 19x19 -> 5x5, smem-staged for coalesced loads.
// 64 images per block. Load 64*361 floats coalesced (float4), compute with
// 64 threads (1 image each, conflict-free smem: 361 % 32 = 9, gcd(9,32)=1),
// store 1600 floats coalesced.
// ---------------------------------------------------------------------------
#define IMGS_PB 64
#define POOL_SMEM_FLOATS (IMGS_PB * IMG)   // 23104
#define POOL_THREADS 256

__global__ __launch_bounds__(POOL_THREADS) void pool_kernel(
    const float* __restrict__ s_in,
    const float* __restrict__ q_in,
    float* __restrict__ out)
{
    extern __shared__ float smem[];            // 23104 floats
    __shared__ float osm[IMGS_PB * P25];       // 1600 floats

    const int blk = blockIdx.x;                // 0..1999
    const int tid = threadIdx.x;
    const int sel = (blk >= 1000) ? 1 : 0;
    const int lblk = blk - sel * 1000;         // 0..999 within tensor

    // ---- coalesced staged load (float4; 23104 = 5776 float4) ----
    const float4* __restrict__ src4 = (const float4*)(
        (sel ? q_in : s_in) + (size_t)lblk * POOL_SMEM_FLOATS);
    float4* __restrict__ smem4 = (float4*)smem;
#pragma unroll
    for (int i = tid; i < POOL_SMEM_FLOATS / 4; i += POOL_THREADS)
        smem4[i] = src4[i];
    __syncthreads();

    // ---- per-image pooling: threads 0..63 ----
    if (tid < IMGS_PB) {
        const float* __restrict__ img = smem + tid * IMG;

        const int BSTART[NW] = {0, 3, 7, 11, 15};
        const int BEND[NW]   = {4, 8, 12, 16, 19};
        const float INVLEN[NW] = {0.25f, 0.2f, 0.2f, 0.2f, 0.25f};

        float acc[NW][NW];
#pragma unroll
        for (int i = 0; i < NW; i++)
#pragma unroll
            for (int j = 0; j < NW; j++) acc[i][j] = 0.0f;

#pragma unroll
        for (int r = 0; r < W_IN; r++) {
            float row[W_IN];
#pragma unroll
            for (int w = 0; w < W_IN; w++)
                row[w] = img[r * W_IN + w];
            float cs[NW];
#pragma unroll
            for (int j = 0; j < NW; j++) {
                float v = 0.0f;
#pragma unroll
                for (int w = BSTART[j]; w < BEND[j]; w++) v += row[w];
                cs[j] = v;
            }
#pragma unroll
            for (int i = 0; i < NW; i++) {
                if (r >= BSTART[i] && r < BEND[i]) {
#pragma unroll
                    for (int j = 0; j < NW; j++) acc[i][j] += cs[j];
                }
            }
        }
#pragma unroll
        for (int i = 0; i < NW; i++) {
            const float ri = INVLEN[i];
#pragma unroll
            for (int j = 0; j < NW; j++)
                osm[tid * P25 + i * NW + j] = acc[i][j] * ri * INVLEN[j];
        }
    }
    __syncthreads();

    // ---- coalesced store: 64 consecutive images -> 1600 consecutive floats
    // img0 = lblk*64; bs = img0/640; c0 = img0%640 (64 divides 640 so block
    // never crosses a bs boundary)
    const int img0 = lblk * IMGS_PB;
    const int bs = img0 / CCH;
    const int c0 = img0 - bs * CCH;
    float* __restrict__ dst =
        out + (size_t)bs * META_PER_BS + (size_t)(sel * CCH + c0) * P25;
#pragma unroll
    for (int i = tid; i < IMGS_PB * P25; i += POOL_THREADS)
        dst[i] = osm[i];
}

// ---------------------------------------------------------------------------
// Kernel 2: all-pairs cosine similarity + max over query positions.
// 800 threads = 25 warps; warp w owns 5x5 (p,q) tile, lanes split c.
// smem transposed [p][c] with row stride 645 (gcd(645%32=5,32)=1 for norms;
// lane-interleaved c -> always conflict-free in dot loop).
// ---------------------------------------------------------------------------
#define CST 645
#define COS_THREADS 800
#define COS_SMEM_FLOATS (2 * P25 * CST)   // 32250

__global__ __launch_bounds__(COS_THREADS) void cosine_kernel(
    const float* __restrict__ meta,
    float* __restrict__ out)
{
    extern __shared__ float sm[];
    float* __restrict__ sf = sm;              // [25][645]
    float* __restrict__ qf = sm + P25 * CST;  // [25][645]
    __shared__ float sn[P25];
    __shared__ float qn[P25];
    __shared__ float simbuf[P25 * P25];

    const int bs  = blockIdx.x;
    const int tid = threadIdx.x;
    const float* __restrict__ base = meta + (size_t)bs * META_PER_BS;

    // stage with transpose: meta[ch*25 + p] -> (ch<640 ? sf : qf)[p][ch%640]
    for (int i = tid; i < META_PER_BS; i += COS_THREADS) {
        int ch = i / P25;
        int p  = i - ch * P25;
        int c  = ch & (CCH - 1);          // ch % 640? 640 not pow2 -> compute
        c = (ch >= CCH) ? (ch - CCH) : ch;
        float* dstp = (ch >= CCH) ? qf : sf;
        dstp[p * CST + c] = base[i];
    }
    __syncthreads();

    // ---- norms: 50 norms x 16 threads each (uses all 800 threads) ----
    {
        const int nid = tid >> 4;          // 0..49
        const int sub = tid & 15;
        const int p = (nid >= P25) ? (nid - P25) : nid;
        const float* __restrict__ f = ((nid >= P25) ? qf : sf) + p * CST;
        float v = 0.0f;
#pragma unroll 8
        for (int c = sub; c < CCH; c += 16) {
            float x = f[c];
            v += x * x;
        }
#pragma unroll
        for (int off = 8; off; off >>= 1)
            v += __shfl_xor_sync(0xffffffffu, v, off);
        if (sub == 0) {
            if (nid >= P25) qn[p] = sqrtf(v);
            else            sn[p] = sqrtf(v);
        }
    }

    // ---- dots: warp w = (pg,qg) 5x5 tile, lane-parallel over c ----
    {
        const int w = tid >> 5;            // 0..24
        const int lane = tid & 31;
        const int pg = (w / NW) * NW;
        const int qg = (w % NW) * NW;

        float acc[NW][NW];
#pragma unroll
        for (int i = 0; i < NW; i++)
#pragma unroll
            for (int j = 0; j < NW; j++) acc[i][j] = 0.0f;

        for (int k = 0; k < CCH / 32; k++) {
            const int c = k * 32 + lane;
            float sv[NW], qv[NW];
#pragma unroll
            for (int i = 0; i < NW; i++) sv[i] = sf[(pg + i) * CST + c];
#pragma unroll
            for (int j = 0; j < NW; j++) qv[j] = qf[(qg + j) * CST + c];
#pragma unroll
            for (int i = 0; i < NW; i++)
#pragma unroll
                for (int j = 0; j < NW; j++)
                    acc[i][j] = fmaf(sv[i], qv[j], acc[i][j]);
        }
        // reduce 25 accumulators across the 32 lanes
#pragma unroll
        for (int off = 16; off; off >>= 1)
#pragma unroll
            for (int i = 0; i < NW; i++)
#pragma unroll
                for (int j = 0; j < NW; j++)
                    acc[i][j] += __shfl_down_sync(0xffffffffu, acc[i][j], off);

        if (lane == 0) {
#pragma unroll
            for (int i = 0; i < NW; i++)
#pragma unroll
                for (int j = 0; j < NW; j++)
                    simbuf[(pg + i) * P25 + (qg + j)] = acc[i][j];
        }
    }
    __syncthreads();

    // ---- divide by norms + max over q ----
    if (tid < P25) {
        const float snp = sn[tid];
        float m = -INFINITY;
#pragma unroll
        for (int q = 0; q < P25; q++) {
            float den = fmaxf(snp * qn[q], 1e-8f);
            m = fmaxf(m, simbuf[tid * P25 + q] / den);
        }
        out[bs * P25 + tid] = m;
    }
}

extern "C" void kernel_launch(void* const* d_in, const int* in_sizes, int n_in,
                              void* d_out, int out_size)
{
    const float* s_in = (const float*)d_in[0];
    const float* q_in = (const float*)d_in[1];
    float* out = (float*)d_out;

    static bool attr_set = false;
    if (!attr_set) {
        cudaFuncSetAttribute(pool_kernel,
                             cudaFuncAttributeMaxDynamicSharedMemorySize,
                             POOL_SMEM_FLOATS * (int)sizeof(float));
        cudaFuncSetAttribute(cosine_kernel,
                             cudaFuncAttributeMaxDynamicSharedMemorySize,
                             COS_SMEM_FLOATS * (int)sizeof(float));
        attr_set = true;
    }

    pool_kernel<<<2000, POOL_THREADS, POOL_SMEM_FLOATS * sizeof(float)>>>(
        s_in, q_in, out);
    cosine_kernel<<<BSN, COS_THREADS, COS_SMEM_FLOATS * sizeof(float)>>>(
        out, out + META_TOTAL);
}